// round 14
// baseline (speedup 1.0000x reference)
#include <cuda_runtime.h>
#include <cuda_bf16.h>
#include <math.h>
#include <stdint.h>

#define GN 100000
#define GE 1600000
#define GF 500
#define GH1 8
#define GHC 64
#define GC2 7
#define NEG 0.2f
#define NCHUNK 391        // ceil(GN/256)
#define NB8 3125          // GN*8/256 exact
#define GM1_GRID 782      // ceil(GN/128)

// ---------------- scratch ----------------
__device__ int   g_deg[GN];
__device__ int   g_off[GN + 1];
__device__ int   g_cursor[GN];
__device__ int   g_csr[GE];
__device__ int   g_aggr[NCHUNK];
__device__ int   g_scan_count;
__device__ float g_h1[GN * GHC];
__device__ float g_as1[GN * GH1];
__device__ float g_ad1[GN * GH1];
__device__ float g_z[GN * 8];
__device__ float g_as2[GN];
__device__ float g_ad2[GN];
__device__ float g_calib[NB8];
__device__ __nv_bfloat16 g_wh[64 * 512];   // W transposed [n][kk], hi part, zero-padded
__device__ __nv_bfloat16 g_wl[64 * 512];   // lo part

__device__ __forceinline__ float lrelu(float v) { return v > 0.f ? v : NEG * v; }

// FMA-only exp (keeps MUFU free; rel err ~1e-7, valid |x| < 80)
__device__ __forceinline__ float fexp(float x) {
    const float LOG2E = 1.4426950408889634f;
    float t = fmaf(x, LOG2E, 12582912.0f);
    int   ni = __float_as_int(t) - 0x4B400000;
    float n = t - 12582912.0f;
    float f = fmaf(x, LOG2E, -n);
    float p = 0.0013333558f;
    p = fmaf(p, f, 0.0096181291f);
    p = fmaf(p, f, 0.0555041087f);
    p = fmaf(p, f, 0.2402265069f);
    p = fmaf(p, f, 0.6931471806f);
    p = fmaf(p, f, 1.0f);
    return p * __int_as_float((ni + 127) << 23);
}

__device__ __forceinline__ uint32_t smem_u32(const void* p) {
    uint32_t a;
    asm("{ .reg .u64 t; cvta.to.shared.u64 t, %1; cvt.u32.u64 %0, t; }" : "=r"(a) : "l"(p));
    return a;
}

// split one float2 into hi/lo bf16x2 words
__device__ __forceinline__ void cvt2(float2 v, uint32_t& h, uint32_t& l) {
    __nv_bfloat16 hx = __float2bfloat16(v.x), hy = __float2bfloat16(v.y);
    __nv_bfloat16 lx = __float2bfloat16(v.x - __bfloat162float(hx));
    __nv_bfloat16 ly = __float2bfloat16(v.y - __bfloat162float(hy));
    __nv_bfloat162 hb = {hx, hy}, lb = {lx, ly};
    h = *(uint32_t*)&hb;
    l = *(uint32_t*)&lb;
}

// ---------------- CSR init + W pre-conversion (fused) ----------------
__global__ void k_zero_wconv(const float* __restrict__ W) {
    int i = blockIdx.x * blockDim.x + threadIdx.x;
    if (i < GN) g_deg[i] = 0;
    if (i == 0) g_scan_count = 0;
    if (i < 64 * 512) {
        int n = i >> 9, kk = i & 511;
        float w = (kk < GF) ? W[(size_t)kk * 64 + n] : 0.f;
        __nv_bfloat16 h = __float2bfloat16(w);
        g_wh[i] = h;
        g_wl[i] = __float2bfloat16(w - __bfloat162float(h));
    }
}

__global__ void k_hist(const int* __restrict__ ei) {
    int e = blockIdx.x * blockDim.x + threadIdx.x;
    if (e < GE) atomicAdd(&g_deg[ei[GE + e]], 1);
}

// single-pass scan
__global__ void k_scan() {
    __shared__ int sh[256];
    int i = blockIdx.x * 256 + threadIdx.x;
    int v = (i < GN) ? g_deg[i] : 0;
    sh[threadIdx.x] = v;
    __syncthreads();
    for (int d = 1; d < 256; d <<= 1) {
        int t = (threadIdx.x >= d) ? sh[threadIdx.x - d] : 0;
        __syncthreads();
        sh[threadIdx.x] += t;
        __syncthreads();
    }
    int incl = sh[threadIdx.x];
    if (threadIdx.x == 255) {
        g_aggr[blockIdx.x] = incl;
        __threadfence();
        atomicAdd(&g_scan_count, 1);
    }
    if (threadIdx.x == 0) {
        while (atomicAdd(&g_scan_count, 0) < NCHUNK) { }
    }
    __syncthreads();
    int pre = 0;
    for (int b = threadIdx.x; b < blockIdx.x; b += 256) pre += __ldcg(&g_aggr[b]);
    __syncthreads();
    sh[threadIdx.x] = pre;
    __syncthreads();
    for (int d = 128; d > 0; d >>= 1) {
        if (threadIdx.x < d) sh[threadIdx.x] += sh[threadIdx.x + d];
        __syncthreads();
    }
    int o = sh[0] + incl - v;
    if (i < GN) { g_off[i] = o; g_cursor[i] = o; }
    if (i == 0) g_off[GN] = GE;
}

__global__ void k_scatter(const int* __restrict__ ei) {
    int e = blockIdx.x * blockDim.x + threadIdx.x;
    if (e < GE) {
        int dst = ei[GE + e];
        int pos = atomicAdd(&g_cursor[dst], 1);
        g_csr[pos] = ei[e];
    }
}

// ---------------- GEMM1: cp.async double-buffered A (raw fp32) + B; reg-convert A ----------------
#define SAW 36                        // B row stride in words
#define BBUF_WORDS (64 * SAW)         // 2304 words per part
#define B_BYTES (2 * 2 * BBUF_WORDS * 4)   // 36864
#define ASTR 72                       // rawA row stride in floats (2-way-conflict banks)
#define ABUF (128 * ASTR)             // 9216 floats per buffer
#define OFF_RAWA B_BYTES              // bytes
#define SMEM_TOT (B_BYTES + 2 * ABUF * 4)  // 36864 + 73728 = 110592

#define MMA_BF16S(c, a, b0v, b1v) \
    asm volatile("mma.sync.aligned.m16n8k16.row.col.f32.bf16.bf16.f32 " \
        "{%0,%1,%2,%3}, {%4,%5,%6,%7}, {%8,%9}, {%0,%1,%2,%3};" \
        : "+f"((c)[0]), "+f"((c)[1]), "+f"((c)[2]), "+f"((c)[3]) \
        : "r"((a)[0]), "r"((a)[1]), "r"((a)[2]), "r"((a)[3]), "r"(b0v), "r"(b1v))

#define LDSM4(r, addr) \
    asm volatile("ldmatrix.sync.aligned.m8n8.x4.shared.b16 {%0,%1,%2,%3}, [%4];" \
        : "=r"((r)[0]), "=r"((r)[1]), "=r"((r)[2]), "=r"((r)[3]) : "r"(addr))

__global__ __launch_bounds__(256, 2) void k_gemm1_tc(const float* __restrict__ x,
                                                     const float* __restrict__ att_s,
                                                     const float* __restrict__ att_d) {
    extern __shared__ char smem[];
    uint32_t* B32 = (uint32_t*)smem;                 // [buf][part][64*SAW]
    float* rawA = (float*)(smem + OFF_RAWA);         // [buf][128*ASTR]

    int tid = threadIdx.x, wid = tid >> 5, lid = tid & 31;
    int g = lid >> 2, tg = lid & 3;
    int brow = blockIdx.x * 128;

    int r0 = brow + wid * 16 + g;
    int r1 = r0 + 8;
    bool ok0 = r0 < GN, ok1 = r1 < GN;
    int rl0 = wid * 16 + g, rl1 = rl0 + 8;

    float acc[8][4] = {};

    auto prefetchB = [&](int st, int buf) {
        int k0 = st * 64;
        uint32_t* base = B32 + buf * 2 * BBUF_WORDS;
        for (int slot = tid; slot < 1024; slot += 256) {
            int part = slot >> 9, i = slot & 511;
            int n = i >> 3, c = i & 7;
            uint32_t dst = smem_u32(base + part * BBUF_WORDS + n * SAW + c * 4);
            const __nv_bfloat16* src = (part ? g_wl : g_wh) + n * 512 + k0 + c * 8;
            asm volatile("cp.async.cg.shared.global [%0], [%1], 16;" :: "r"(dst), "l"(src));
        }
    };

    auto prefetchA = [&](int st, int buf) {
        int k0 = st * 64;
        float* base = rawA + buf * ABUF;
        for (int slot = tid; slot < 2048; slot += 256) {
            int r = slot >> 4, f4 = slot & 15;
            int row = brow + r, k = k0 + f4 * 4;
            uint32_t dst = smem_u32(base + r * ASTR + f4 * 4);
            if (row < GN && k + 3 < GF) {
                const float* src = x + (size_t)row * GF + k;
                asm volatile("cp.async.cg.shared.global [%0], [%1], 16;" :: "r"(dst), "l"(src));
            } else {
                asm volatile("st.shared.v4.b32 [%0], {%1,%1,%1,%1};" :: "r"(dst), "r"(0) : "memory");
            }
        }
    };

    prefetchB(0, 0);
    prefetchA(0, 0);
    asm volatile("cp.async.commit_group;" ::: "memory");
    asm volatile("cp.async.wait_group 0;" ::: "memory");
    __syncthreads();

    for (int st = 0; st < 8; st++) {
        int buf = st & 1;
        if (st < 7) {
            prefetchB(st + 1, buf ^ 1);
            prefetchA(st + 1, buf ^ 1);
            asm volatile("cp.async.commit_group;" ::: "memory");
        }

        uint32_t* bh = B32 + buf * 2 * BBUF_WORDS;
        uint32_t* bl = bh + BBUF_WORDS;
        uint32_t bhA = smem_u32(bh + lid * SAW);
        uint32_t bhB = smem_u32(bh + (32 + lid) * SAW);
        uint32_t blA = smem_u32(bl + lid * SAW);
        uint32_t blB = smem_u32(bl + (32 + lid) * SAW);
        const float* aBase = rawA + buf * ABUF;

#pragma unroll
        for (int ks = 0; ks < 4; ks++) {
            int kl = ks * 16 + 2 * tg;
            float2 a00 = *(const float2*)(aBase + rl0 * ASTR + kl);
            float2 a10 = *(const float2*)(aBase + rl1 * ASTR + kl);
            float2 a01 = *(const float2*)(aBase + rl0 * ASTR + kl + 8);
            float2 a11 = *(const float2*)(aBase + rl1 * ASTR + kl + 8);
            uint32_t ah[4], al[4];
            cvt2(a00, ah[0], al[0]);
            cvt2(a10, ah[1], al[1]);
            cvt2(a01, ah[2], al[2]);
            cvt2(a11, ah[3], al[3]);

            uint32_t b0hA[4], b1hA[4], b0hB[4], b1hB[4];
            uint32_t b0lA[4], b1lA[4], b0lB[4], b1lB[4];
            LDSM4(b0hA, bhA + ks * 32);
            LDSM4(b1hA, bhA + ks * 32 + 16);
            LDSM4(b0hB, bhB + ks * 32);
            LDSM4(b1hB, bhB + ks * 32 + 16);
            LDSM4(b0lA, blA + ks * 32);
            LDSM4(b1lA, blA + ks * 32 + 16);
            LDSM4(b0lB, blB + ks * 32);
            LDSM4(b1lB, blB + ks * 32 + 16);

#pragma unroll
            for (int fn = 0; fn < 8; fn++) {
                uint32_t b0h = (fn < 4) ? b0hA[fn] : b0hB[fn - 4];
                uint32_t b1h = (fn < 4) ? b1hA[fn] : b1hB[fn - 4];
                uint32_t b0l = (fn < 4) ? b0lA[fn] : b0lB[fn - 4];
                uint32_t b1l = (fn < 4) ? b1lA[fn] : b1lB[fn - 4];
                MMA_BF16S(acc[fn], ah, b0h, b1h);
                MMA_BF16S(acc[fn], ah, b0l, b1l);
                MMA_BF16S(acc[fn], al, b0h, b1h);
            }
        }

        if (st < 7) {
            asm volatile("cp.async.wait_group 0;" ::: "memory");
            __syncthreads();
        }
    }

    // ---- epilogue: write h1 + fused as1/ad1 (head h == fn)
    float as_c[8][2], ad_c[8][2];
#pragma unroll
    for (int fn = 0; fn < 8; fn++) {
        int col = fn * 8 + tg * 2;
        as_c[fn][0] = __ldg(&att_s[col]);     as_c[fn][1] = __ldg(&att_s[col + 1]);
        ad_c[fn][0] = __ldg(&att_d[col]);     ad_c[fn][1] = __ldg(&att_d[col + 1]);
    }
    float sh0[8], dh0[8], sh1[8], dh1[8];
#pragma unroll
    for (int fn = 0; fn < 8; fn++) {
        int col = fn * 8 + tg * 2;
        float c0 = acc[fn][0], c1 = acc[fn][1], c2 = acc[fn][2], c3 = acc[fn][3];
        if (ok0) *(float2*)&g_h1[(size_t)r0 * GHC + col] = make_float2(c0, c1);
        if (ok1) *(float2*)&g_h1[(size_t)r1 * GHC + col] = make_float2(c2, c3);
        sh0[fn] = c0 * as_c[fn][0] + c1 * as_c[fn][1];
        dh0[fn] = c0 * ad_c[fn][0] + c1 * ad_c[fn][1];
        sh1[fn] = c2 * as_c[fn][0] + c3 * as_c[fn][1];
        dh1[fn] = c2 * ad_c[fn][0] + c3 * ad_c[fn][1];
    }
#pragma unroll
    for (int w = 1; w < 4; w <<= 1)
#pragma unroll
        for (int fn = 0; fn < 8; fn++) {
            sh0[fn] += __shfl_xor_sync(0xffffffffu, sh0[fn], w, 4);
            dh0[fn] += __shfl_xor_sync(0xffffffffu, dh0[fn], w, 4);
            sh1[fn] += __shfl_xor_sync(0xffffffffu, sh1[fn], w, 4);
            dh1[fn] += __shfl_xor_sync(0xffffffffu, dh1[fn], w, 4);
        }
    if (tg == 0) {
#pragma unroll
        for (int fn = 0; fn < 8; fn++) {
            if (ok0) { g_as1[r0 * 8 + fn] = sh0[fn]; g_ad1[r0 * 8 + fn] = dh0[fn]; }
            if (ok1) { g_as1[r1 * 8 + fn] = sh1[fn]; g_ad1[r1 * 8 + fn] = dh1[fn]; }
        }
    }
}

// ---------------- layer-1 agg (thread-per-(node,head)) + fused GEMM2/alphas2 ----------------
__global__ __launch_bounds__(256) void k_agg1(const float* __restrict__ b1,
                                              const float* __restrict__ mask,
                                              const float* __restrict__ W2,
                                              const float* __restrict__ as2v,
                                              const float* __restrict__ ad2v) {
    __shared__ float sw[448], sas[7], sad[7];
    for (int i = threadIdx.x; i < 448; i += 256) sw[i] = W2[i];
    if (threadIdx.x < 7) { sas[threadIdx.x] = as2v[threadIdx.x]; sad[threadIdx.x] = ad2v[threadIdx.x]; }
    __syncthreads();

    int gid = blockIdx.x * 256 + threadIdx.x;   // GN*8 exact
    int node = gid >> 3, h = gid & 7;
    float adst = g_ad1[gid];
    float s = fexp(lrelu(g_as1[gid] + adst));     // self edge
    const float4* selfp = (const float4*)(g_h1 + (size_t)node * GHC + h * 8);
    float4 sv0 = selfp[0], sv1 = selfp[1];
    float4 a0 = make_float4(s * sv0.x, s * sv0.y, s * sv0.z, s * sv0.w);
    float4 a1 = make_float4(s * sv1.x, s * sv1.y, s * sv1.z, s * sv1.w);
    int beg = g_off[node], end = g_off[node + 1];
    for (int i = beg; i < end; i++) {
        int src = g_csr[i];
        float w = fexp(lrelu(__ldg(&g_as1[src * GH1 + h]) + adst));
        const float4* hp = (const float4*)(g_h1 + (size_t)src * GHC + h * 8);
        float4 v0 = __ldg(hp), v1 = __ldg(hp + 1);
        s += w;
        a0.x += w * v0.x; a0.y += w * v0.y; a0.z += w * v0.z; a0.w += w * v0.w;
        a1.x += w * v1.x; a1.y += w * v1.y; a1.z += w * v1.z; a1.w += w * v1.w;
    }
    float inv = 1.0f / (s + 1e-16f);
    float hp8[8] = {a0.x, a0.y, a0.z, a0.w, a1.x, a1.y, a1.z, a1.w};
    int base = node * GHC + h * 8;
#pragma unroll
    for (int c = 0; c < 8; c++) {
        float v = hp8[c] * inv + b1[h * 8 + c];
        hp8[c] = fmaxf(v, 0.f) * mask[base + c];
    }
    float z[7] = {};
#pragma unroll
    for (int c = 0; c < 8; c++) {
        float hv = hp8[c];
        const float* wr = &sw[(h * 8 + c) * 7];
#pragma unroll
        for (int j = 0; j < 7; j++) z[j] += hv * wr[j];
    }
#pragma unroll
    for (int w = 1; w < 8; w <<= 1)
#pragma unroll
        for (int j = 0; j < 7; j++) z[j] += __shfl_xor_sync(0xffffffffu, z[j], w, 8);
    if (h == 0) {
        float as = 0.f, ad = 0.f;
        float* zp = g_z + (size_t)node * 8;
#pragma unroll
        for (int j = 0; j < 7; j++) {
            as += z[j] * sas[j];
            ad += z[j] * sad[j];
            zp[j] = z[j];
        }
        zp[7] = 0.f;
        g_as2[node] = as;
        g_ad2[node] = ad;
    }
}

// ---------------- layer-2 agg (8 lanes/node) + epilogue ----------------
__global__ __launch_bounds__(256) void k_agg2(const float* __restrict__ b2,
                                              float* __restrict__ out) {
    int gid = blockIdx.x * 256 + threadIdx.x;    // GN*8 exact
    int node = gid >> 3, c = gid & 7;
    float adst = g_ad2[node];
    float s = fexp(lrelu(g_as2[node] + adst));
    float acc = s * g_z[(size_t)node * 8 + c];
    int beg = g_off[node], end = g_off[node + 1];
    for (int i = beg; i < end; i++) {
        int src = g_csr[i];
        float w = fexp(lrelu(__ldg(&g_as2[src]) + adst));
        s += w;
        acc += w * __ldg(&g_z[(size_t)src * 8 + c]);
    }
    float xo = acc / (s + 1e-16f) + ((c < 7) ? b2[c] : 0.f);
    float xv = (c < 7) ? xo : -1e30f;
    float mx = xv;
#pragma unroll
    for (int w = 1; w < 8; w <<= 1) mx = fmaxf(mx, __shfl_xor_sync(0xffffffffu, mx, w, 8));
    float e = (c < 7) ? fexp(xo - mx) : 0.f;
    float sum = e;
#pragma unroll
    for (int w = 1; w < 8; w <<= 1) sum += __shfl_xor_sync(0xffffffffu, sum, w, 8);
    float lse = __logf(sum);
    float p = e / sum;
    if (c < 7) {
        out[(size_t)node * 7 + c] = xo - mx - lse;          // log_softmax
        out[700001 + (size_t)node * 7 + c] = p;             // softmax
    }
    float p1 = -1.f, p2 = -1.f;
#pragma unroll
    for (int j = 0; j < 7; j++) {
        float pj = __shfl_sync(0xffffffffu, p, j, 8);
        if (pj > p1) { p2 = p1; p1 = pj; }
        else if (pj > p2) { p2 = pj; }
    }
    float calib = (c == 0) ? (1.0f - p1 + p2) : 0.f;
    __shared__ float red[256];
    red[threadIdx.x] = calib;
    __syncthreads();
    for (int d = 128; d > 0; d >>= 1) {
        if (threadIdx.x < d) red[threadIdx.x] += red[threadIdx.x + d];
        __syncthreads();
    }
    if (threadIdx.x == 0) g_calib[blockIdx.x] = red[0];
}

__global__ void k_final(float* __restrict__ out) {
    __shared__ float sh[1024];
    float s = 0.f;
    for (int i = threadIdx.x; i < NB8; i += 1024) s += g_calib[i];
    sh[threadIdx.x] = s;
    __syncthreads();
    for (int d = 512; d > 0; d >>= 1) {
        if (threadIdx.x < d) sh[threadIdx.x] += sh[threadIdx.x + d];
        __syncthreads();
    }
    if (threadIdx.x == 0) out[700000] = sh[0] / (float)GN;
}

// ---------------- launch: gemm1 stays 4th submitted kernel (ncu window) ----------------
extern "C" void kernel_launch(void* const* d_in, const int* in_sizes, int n_in,
                              void* d_out, int out_size) {
    const float* x        = (const float*)d_in[0];
    const int*   ei       = (const int*)d_in[1];
    const float* mask     = (const float*)d_in[2];
    const float* W1       = (const float*)d_in[3];
    const float* att_s1   = (const float*)d_in[4];
    const float* att_d1   = (const float*)d_in[5];
    const float* b1       = (const float*)d_in[6];
    const float* W2       = (const float*)d_in[7];
    const float* att_s2   = (const float*)d_in[8];
    const float* att_d2   = (const float*)d_in[9];
    const float* b2       = (const float*)d_in[10];
    float* out = (float*)d_out;

    static cudaStream_t s2 = nullptr;
    static cudaEvent_t evFork = nullptr, evW = nullptr, evJoin = nullptr;
    if (s2 == nullptr) {
        cudaStreamCreateWithFlags(&s2, cudaStreamNonBlocking);
        cudaEventCreateWithFlags(&evFork, cudaEventDisableTiming);
        cudaEventCreateWithFlags(&evW, cudaEventDisableTiming);
        cudaEventCreateWithFlags(&evJoin, cudaEventDisableTiming);
        cudaFuncSetAttribute(k_gemm1_tc, cudaFuncAttributeMaxDynamicSharedMemorySize, SMEM_TOT);
    }

    const int TB = 256;
    int eg = (GE + TB - 1) / TB;

    cudaEventRecord(evFork, 0);
    cudaStreamWaitEvent(s2, evFork, 0);
    k_zero_wconv<<<NCHUNK, TB, 0, s2>>>(W1);      // #1 (also converts W)
    cudaEventRecord(evW, s2);
    k_hist<<<eg, TB, 0, s2>>>(ei);                // #2
    k_scan<<<NCHUNK, TB, 0, s2>>>();              // #3
    cudaStreamWaitEvent(0, evW, 0);               // gemm1 needs g_wh/g_wl
    k_gemm1_tc<<<GM1_GRID, TB, SMEM_TOT>>>(x, att_s1, att_d1);   // #4 (main)
    k_scatter<<<eg, TB, 0, s2>>>(ei);             // #5 (side)
    cudaEventRecord(evJoin, s2);
    cudaStreamWaitEvent(0, evJoin, 0);

    k_agg1<<<NB8, TB>>>(b1, mask, W2, att_s2, att_d2);   // #6
    k_agg2<<<NB8, TB>>>(b2, out);                        // #7
    k_final<<<1, 1024>>>(out);                           // #8
}

// round 15
// speedup vs baseline: 1.0284x; 1.0284x over previous
#include <cuda_runtime.h>
#include <cuda_bf16.h>
#include <cuda_fp16.h>
#include <math.h>
#include <stdint.h>

#define GN 100000
#define GE 1600000
#define GF 500
#define GH1 8
#define GHC 64
#define GC2 7
#define NEG 0.2f
#define NCHUNK 391        // ceil(GN/256)
#define NB8 3125          // GN*8/256 exact
#define GM1_GRID 782      // ceil(GN/128)

// ---------------- scratch ----------------
__device__ int   g_deg[GN];
__device__ int   g_off[GN + 1];
__device__ int   g_cursor[GN];
__device__ int   g_csr[GE];
__device__ int   g_aggr[NCHUNK];
__device__ int   g_scan_count;
__device__ int   g_done;
__device__ __half g_h1h[GN * GHC];        // layer1 features, fp16 (message payload)
__device__ float g_as1[GN * GH1];
__device__ float g_ad1[GN * GH1];
__device__ __half g_zh[GN * 8];           // layer2 features, fp16
__device__ float g_as2[GN];
__device__ float g_ad2[GN];
__device__ float g_calib[NB8];
__device__ __nv_bfloat16 g_wh[64 * 512];  // W transposed [n][kk], hi, zero-padded
__device__ __nv_bfloat16 g_wl[64 * 512];  // lo

__device__ __forceinline__ float lrelu(float v) { return v > 0.f ? v : NEG * v; }

// FMA-only exp (keeps MUFU free; rel err ~1e-7, valid |x| < 80)
__device__ __forceinline__ float fexp(float x) {
    const float LOG2E = 1.4426950408889634f;
    float t = fmaf(x, LOG2E, 12582912.0f);
    int   ni = __float_as_int(t) - 0x4B400000;
    float n = t - 12582912.0f;
    float f = fmaf(x, LOG2E, -n);
    float p = 0.0013333558f;
    p = fmaf(p, f, 0.0096181291f);
    p = fmaf(p, f, 0.0555041087f);
    p = fmaf(p, f, 0.2402265069f);
    p = fmaf(p, f, 0.6931471806f);
    p = fmaf(p, f, 1.0f);
    return p * __int_as_float((ni + 127) << 23);
}

__device__ __forceinline__ uint32_t smem_u32(const void* p) {
    uint32_t a;
    asm("{ .reg .u64 t; cvta.to.shared.u64 t, %1; cvt.u32.u64 %0, t; }" : "=r"(a) : "l"(p));
    return a;
}

// split float2 -> hi/lo bf16x2 words; 1 pack + extract + 2 sub + 1 pack
__device__ __forceinline__ void cvt2(float2 v, uint32_t& h, uint32_t& l) {
    uint32_t hp;
    asm("cvt.rn.bf16x2.f32 %0, %1, %2;" : "=r"(hp) : "f"(v.y), "f"(v.x));
    float hx = __int_as_float(hp << 16);
    float hy = __int_as_float(hp & 0xFFFF0000u);
    float lx = v.x - hx, ly = v.y - hy;
    asm("cvt.rn.bf16x2.f32 %0, %1, %2;" : "=r"(l) : "f"(ly), "f"(lx));
    h = hp;
}

__device__ __forceinline__ void unpack8(uint4 pk, float* f) {
    const __half2* hp = (const __half2*)&pk;
#pragma unroll
    for (int i = 0; i < 4; i++) {
        float2 t = __half22float2(hp[i]);
        f[2 * i] = t.x;
        f[2 * i + 1] = t.y;
    }
}

// ---------------- CSR init + W pre-conversion (fused) ----------------
__global__ void k_zero_wconv(const float* __restrict__ W) {
    int i = blockIdx.x * blockDim.x + threadIdx.x;
    if (i < GN) g_deg[i] = 0;
    if (i == 0) { g_scan_count = 0; g_done = 0; }
    if (i < 64 * 512) {
        int n = i >> 9, kk = i & 511;
        float w = (kk < GF) ? W[(size_t)kk * 64 + n] : 0.f;
        __nv_bfloat16 h = __float2bfloat16(w);
        g_wh[i] = h;
        g_wl[i] = __float2bfloat16(w - __bfloat162float(h));
    }
}

__global__ void k_hist(const int* __restrict__ ei) {
    int e = blockIdx.x * blockDim.x + threadIdx.x;
    if (e < GE) atomicAdd(&g_deg[ei[GE + e]], 1);
}

// single-pass scan
__global__ void k_scan() {
    __shared__ int sh[256];
    int i = blockIdx.x * 256 + threadIdx.x;
    int v = (i < GN) ? g_deg[i] : 0;
    sh[threadIdx.x] = v;
    __syncthreads();
    for (int d = 1; d < 256; d <<= 1) {
        int t = (threadIdx.x >= d) ? sh[threadIdx.x - d] : 0;
        __syncthreads();
        sh[threadIdx.x] += t;
        __syncthreads();
    }
    int incl = sh[threadIdx.x];
    if (threadIdx.x == 255) {
        g_aggr[blockIdx.x] = incl;
        __threadfence();
        atomicAdd(&g_scan_count, 1);
    }
    if (threadIdx.x == 0) {
        while (atomicAdd(&g_scan_count, 0) < NCHUNK) { }
    }
    __syncthreads();
    int pre = 0;
    for (int b = threadIdx.x; b < blockIdx.x; b += 256) pre += __ldcg(&g_aggr[b]);
    __syncthreads();
    sh[threadIdx.x] = pre;
    __syncthreads();
    for (int d = 128; d > 0; d >>= 1) {
        if (threadIdx.x < d) sh[threadIdx.x] += sh[threadIdx.x + d];
        __syncthreads();
    }
    int o = sh[0] + incl - v;
    if (i < GN) { g_off[i] = o; g_cursor[i] = o; }
    if (i == 0) g_off[GN] = GE;
}

__global__ void k_scatter(const int* __restrict__ ei) {
    int e = blockIdx.x * blockDim.x + threadIdx.x;
    if (e < GE) {
        int dst = ei[GE + e];
        int pos = atomicAdd(&g_cursor[dst], 1);
        g_csr[pos] = ei[e];
    }
}

// ---------------- GEMM1: cp.async double-buffered A (raw fp32) + B; reg-convert A ----------------
#define SAW 36
#define BBUF_WORDS (64 * SAW)
#define B_BYTES (2 * 2 * BBUF_WORDS * 4)   // 36864
#define ASTR 72
#define ABUF (128 * ASTR)
#define OFF_RAWA B_BYTES
#define SMEM_TOT (B_BYTES + 2 * ABUF * 4)  // 110592

#define MMA_BF16S(c, a, b0v, b1v) \
    asm volatile("mma.sync.aligned.m16n8k16.row.col.f32.bf16.bf16.f32 " \
        "{%0,%1,%2,%3}, {%4,%5,%6,%7}, {%8,%9}, {%0,%1,%2,%3};" \
        : "+f"((c)[0]), "+f"((c)[1]), "+f"((c)[2]), "+f"((c)[3]) \
        : "r"((a)[0]), "r"((a)[1]), "r"((a)[2]), "r"((a)[3]), "r"(b0v), "r"(b1v))

#define LDSM4(r, addr) \
    asm volatile("ldmatrix.sync.aligned.m8n8.x4.shared.b16 {%0,%1,%2,%3}, [%4];" \
        : "=r"((r)[0]), "=r"((r)[1]), "=r"((r)[2]), "=r"((r)[3]) : "r"(addr))

__global__ __launch_bounds__(256, 2) void k_gemm1_tc(const float* __restrict__ x,
                                                     const float* __restrict__ att_s,
                                                     const float* __restrict__ att_d) {
    extern __shared__ char smem[];
    uint32_t* B32 = (uint32_t*)smem;
    float* rawA = (float*)(smem + OFF_RAWA);

    int tid = threadIdx.x, wid = tid >> 5, lid = tid & 31;
    int g = lid >> 2, tg = lid & 3;
    int brow = blockIdx.x * 128;

    int r0 = brow + wid * 16 + g;
    int r1 = r0 + 8;
    bool ok0 = r0 < GN, ok1 = r1 < GN;
    int rl0 = wid * 16 + g, rl1 = rl0 + 8;

    float acc[8][4] = {};

    auto prefetchB = [&](int st, int buf) {
        int k0 = st * 64;
        uint32_t* base = B32 + buf * 2 * BBUF_WORDS;
        for (int slot = tid; slot < 1024; slot += 256) {
            int part = slot >> 9, i = slot & 511;
            int n = i >> 3, c = i & 7;
            uint32_t dst = smem_u32(base + part * BBUF_WORDS + n * SAW + c * 4);
            const __nv_bfloat16* src = (part ? g_wl : g_wh) + n * 512 + k0 + c * 8;
            asm volatile("cp.async.cg.shared.global [%0], [%1], 16;" :: "r"(dst), "l"(src));
        }
    };

    auto prefetchA = [&](int st, int buf) {
        int k0 = st * 64;
        float* base = rawA + buf * ABUF;
        for (int slot = tid; slot < 2048; slot += 256) {
            int r = slot >> 4, f4 = slot & 15;
            int row = brow + r, k = k0 + f4 * 4;
            uint32_t dst = smem_u32(base + r * ASTR + f4 * 4);
            if (row < GN && k + 3 < GF) {
                const float* src = x + (size_t)row * GF + k;
                asm volatile("cp.async.cg.shared.global [%0], [%1], 16;" :: "r"(dst), "l"(src));
            } else {
                asm volatile("st.shared.v4.b32 [%0], {%1,%1,%1,%1};" :: "r"(dst), "r"(0) : "memory");
            }
        }
    };

    prefetchB(0, 0);
    prefetchA(0, 0);
    asm volatile("cp.async.commit_group;" ::: "memory");
    asm volatile("cp.async.wait_group 0;" ::: "memory");
    __syncthreads();

    for (int st = 0; st < 8; st++) {
        int buf = st & 1;
        if (st < 7) {
            prefetchB(st + 1, buf ^ 1);
            prefetchA(st + 1, buf ^ 1);
            asm volatile("cp.async.commit_group;" ::: "memory");
        }

        uint32_t* bh = B32 + buf * 2 * BBUF_WORDS;
        uint32_t* bl = bh + BBUF_WORDS;
        uint32_t bhA = smem_u32(bh + lid * SAW);
        uint32_t bhB = smem_u32(bh + (32 + lid) * SAW);
        uint32_t blA = smem_u32(bl + lid * SAW);
        uint32_t blB = smem_u32(bl + (32 + lid) * SAW);
        const float* aBase = rawA + buf * ABUF;

#pragma unroll
        for (int ks = 0; ks < 4; ks++) {
            int kl = ks * 16 + 2 * tg;
            float2 a00 = *(const float2*)(aBase + rl0 * ASTR + kl);
            float2 a10 = *(const float2*)(aBase + rl1 * ASTR + kl);
            float2 a01 = *(const float2*)(aBase + rl0 * ASTR + kl + 8);
            float2 a11 = *(const float2*)(aBase + rl1 * ASTR + kl + 8);
            uint32_t ah[4], al[4];
            cvt2(a00, ah[0], al[0]);
            cvt2(a10, ah[1], al[1]);
            cvt2(a01, ah[2], al[2]);
            cvt2(a11, ah[3], al[3]);

            uint32_t b0hA[4], b1hA[4], b0hB[4], b1hB[4];
            uint32_t b0lA[4], b1lA[4], b0lB[4], b1lB[4];
            LDSM4(b0hA, bhA + ks * 32);
            LDSM4(b1hA, bhA + ks * 32 + 16);
            LDSM4(b0hB, bhB + ks * 32);
            LDSM4(b1hB, bhB + ks * 32 + 16);
            LDSM4(b0lA, blA + ks * 32);
            LDSM4(b1lA, blA + ks * 32 + 16);
            LDSM4(b0lB, blB + ks * 32);
            LDSM4(b1lB, blB + ks * 32 + 16);

#pragma unroll
            for (int fn = 0; fn < 8; fn++) {
                uint32_t b0h = (fn < 4) ? b0hA[fn] : b0hB[fn - 4];
                uint32_t b1h = (fn < 4) ? b1hA[fn] : b1hB[fn - 4];
                uint32_t b0l = (fn < 4) ? b0lA[fn] : b0lB[fn - 4];
                uint32_t b1l = (fn < 4) ? b1lA[fn] : b1lB[fn - 4];
                MMA_BF16S(acc[fn], ah, b0h, b1h);
                MMA_BF16S(acc[fn], ah, b0l, b1l);
                MMA_BF16S(acc[fn], al, b0h, b1h);
            }
        }

        if (st < 7) {
            asm volatile("cp.async.wait_group 0;" ::: "memory");
            __syncthreads();
        }
    }

    // ---- epilogue: write h1 (fp16) + fused as1/ad1 (fp32, from exact acc)
    float as_c[8][2], ad_c[8][2];
#pragma unroll
    for (int fn = 0; fn < 8; fn++) {
        int col = fn * 8 + tg * 2;
        as_c[fn][0] = __ldg(&att_s[col]);     as_c[fn][1] = __ldg(&att_s[col + 1]);
        ad_c[fn][0] = __ldg(&att_d[col]);     ad_c[fn][1] = __ldg(&att_d[col + 1]);
    }
    float sh0[8], dh0[8], sh1[8], dh1[8];
#pragma unroll
    for (int fn = 0; fn < 8; fn++) {
        int col = fn * 8 + tg * 2;
        float c0 = acc[fn][0], c1 = acc[fn][1], c2 = acc[fn][2], c3 = acc[fn][3];
        if (ok0) *(__half2*)&g_h1h[(size_t)r0 * GHC + col] = __floats2half2_rn(c0, c1);
        if (ok1) *(__half2*)&g_h1h[(size_t)r1 * GHC + col] = __floats2half2_rn(c2, c3);
        sh0[fn] = c0 * as_c[fn][0] + c1 * as_c[fn][1];
        dh0[fn] = c0 * ad_c[fn][0] + c1 * ad_c[fn][1];
        sh1[fn] = c2 * as_c[fn][0] + c3 * as_c[fn][1];
        dh1[fn] = c2 * ad_c[fn][0] + c3 * ad_c[fn][1];
    }
#pragma unroll
    for (int w = 1; w < 4; w <<= 1)
#pragma unroll
        for (int fn = 0; fn < 8; fn++) {
            sh0[fn] += __shfl_xor_sync(0xffffffffu, sh0[fn], w, 4);
            dh0[fn] += __shfl_xor_sync(0xffffffffu, dh0[fn], w, 4);
            sh1[fn] += __shfl_xor_sync(0xffffffffu, sh1[fn], w, 4);
            dh1[fn] += __shfl_xor_sync(0xffffffffu, dh1[fn], w, 4);
        }
    if (tg == 0) {
#pragma unroll
        for (int fn = 0; fn < 8; fn++) {
            if (ok0) { g_as1[r0 * 8 + fn] = sh0[fn]; g_ad1[r0 * 8 + fn] = dh0[fn]; }
            if (ok1) { g_as1[r1 * 8 + fn] = sh1[fn]; g_ad1[r1 * 8 + fn] = dh1[fn]; }
        }
    }
}

// ---------------- layer-1 agg (thread-per-(node,head), fp16 gather) + fused GEMM2/alphas2 ----------------
__global__ __launch_bounds__(256) void k_agg1(const float* __restrict__ b1,
                                              const float* __restrict__ mask,
                                              const float* __restrict__ W2,
                                              const float* __restrict__ as2v,
                                              const float* __restrict__ ad2v) {
    __shared__ float sw[448], sas[7], sad[7];
    for (int i = threadIdx.x; i < 448; i += 256) sw[i] = W2[i];
    if (threadIdx.x < 7) { sas[threadIdx.x] = as2v[threadIdx.x]; sad[threadIdx.x] = ad2v[threadIdx.x]; }
    __syncthreads();

    int gid = blockIdx.x * 256 + threadIdx.x;   // GN*8 exact
    int node = gid >> 3, h = gid & 7;
    float adst = g_ad1[gid];
    float s = fexp(lrelu(g_as1[gid] + adst));     // self edge
    float f[8], ac[8];
    unpack8(*(const uint4*)(g_h1h + (size_t)node * GHC + h * 8), f);
#pragma unroll
    for (int c = 0; c < 8; c++) ac[c] = s * f[c];
    int beg = g_off[node], end = g_off[node + 1];
    for (int i = beg; i < end; i++) {
        int src = g_csr[i];
        float w = fexp(lrelu(__ldg(&g_as1[src * GH1 + h]) + adst));
        uint4 pk = __ldg((const uint4*)(g_h1h + (size_t)src * GHC + h * 8));
        unpack8(pk, f);
        s += w;
#pragma unroll
        for (int c = 0; c < 8; c++) ac[c] += w * f[c];
    }
    float inv = 1.0f / (s + 1e-16f);
    int base = node * GHC + h * 8;
    float z[7] = {};
#pragma unroll
    for (int c = 0; c < 8; c++) {
        float v = ac[c] * inv + b1[h * 8 + c];
        float hv = fmaxf(v, 0.f) * mask[base + c];
        const float* wr = &sw[(h * 8 + c) * 7];
#pragma unroll
        for (int j = 0; j < 7; j++) z[j] += hv * wr[j];
    }
#pragma unroll
    for (int w = 1; w < 8; w <<= 1)
#pragma unroll
        for (int j = 0; j < 7; j++) z[j] += __shfl_xor_sync(0xffffffffu, z[j], w, 8);
    if (h == 0) {
        float as = 0.f, ad = 0.f;
        __half zh[8];
#pragma unroll
        for (int j = 0; j < 7; j++) {
            as += z[j] * sas[j];
            ad += z[j] * sad[j];
            zh[j] = __float2half(z[j]);
        }
        zh[7] = __float2half(0.f);
        *(uint4*)(g_zh + (size_t)node * 8) = *(uint4*)zh;
        g_as2[node] = as;
        g_ad2[node] = ad;
    }
}

// ---------------- layer-2 agg (8 lanes/node, fp16 z) + epilogue + fused final ----------------
__global__ __launch_bounds__(256) void k_agg2(const float* __restrict__ b2,
                                              float* __restrict__ out) {
    int gid = blockIdx.x * 256 + threadIdx.x;    // GN*8 exact
    int node = gid >> 3, c = gid & 7;
    float adst = g_ad2[node];
    float s = fexp(lrelu(g_as2[node] + adst));
    float acc = s * __half2float(g_zh[(size_t)node * 8 + c]);
    int beg = g_off[node], end = g_off[node + 1];
    for (int i = beg; i < end; i++) {
        int src = g_csr[i];
        float w = fexp(lrelu(__ldg(&g_as2[src]) + adst));
        s += w;
        acc += w * __half2float(__ldg(&g_zh[(size_t)src * 8 + c]));
    }
    float xo = acc / (s + 1e-16f) + ((c < 7) ? b2[c] : 0.f);
    float xv = (c < 7) ? xo : -1e30f;
    float mx = xv;
#pragma unroll
    for (int w = 1; w < 8; w <<= 1) mx = fmaxf(mx, __shfl_xor_sync(0xffffffffu, mx, w, 8));
    float e = (c < 7) ? fexp(xo - mx) : 0.f;
    float sum = e;
#pragma unroll
    for (int w = 1; w < 8; w <<= 1) sum += __shfl_xor_sync(0xffffffffu, sum, w, 8);
    float lse = __logf(sum);
    float p = e / sum;
    if (c < 7) {
        out[(size_t)node * 7 + c] = xo - mx - lse;          // log_softmax
        out[700001 + (size_t)node * 7 + c] = p;             // softmax
    }
    float p1 = -1.f, p2 = -1.f;
#pragma unroll
    for (int j = 0; j < 7; j++) {
        float pj = __shfl_sync(0xffffffffu, p, j, 8);
        if (pj > p1) { p2 = p1; p1 = pj; }
        else if (pj > p2) { p2 = pj; }
    }
    float calib = (c == 0) ? (1.0f - p1 + p2) : 0.f;
    __shared__ float red[256];
    __shared__ int lastFlag;
    red[threadIdx.x] = calib;
    __syncthreads();
    for (int d = 128; d > 0; d >>= 1) {
        if (threadIdx.x < d) red[threadIdx.x] += red[threadIdx.x + d];
        __syncthreads();
    }
    if (threadIdx.x == 0) {
        g_calib[blockIdx.x] = red[0];
        __threadfence();
        int t = atomicAdd(&g_done, 1);
        lastFlag = (t == NB8 - 1);
    }
    __syncthreads();
    if (lastFlag) {           // last block: deterministic fixed-order reduction
        float sum2 = 0.f;
        for (int i = threadIdx.x; i < NB8; i += 256) sum2 += __ldcg(&g_calib[i]);
        red[threadIdx.x] = sum2;
        __syncthreads();
        for (int d = 128; d > 0; d >>= 1) {
            if (threadIdx.x < d) red[threadIdx.x] += red[threadIdx.x + d];
            __syncthreads();
        }
        if (threadIdx.x == 0) out[700000] = red[0] / (float)GN;
    }
}

// ---------------- launch: gemm1 stays 4th submitted kernel (ncu window) ----------------
extern "C" void kernel_launch(void* const* d_in, const int* in_sizes, int n_in,
                              void* d_out, int out_size) {
    const float* x        = (const float*)d_in[0];
    const int*   ei       = (const int*)d_in[1];
    const float* mask     = (const float*)d_in[2];
    const float* W1       = (const float*)d_in[3];
    const float* att_s1   = (const float*)d_in[4];
    const float* att_d1   = (const float*)d_in[5];
    const float* b1       = (const float*)d_in[6];
    const float* W2       = (const float*)d_in[7];
    const float* att_s2   = (const float*)d_in[8];
    const float* att_d2   = (const float*)d_in[9];
    const float* b2       = (const float*)d_in[10];
    float* out = (float*)d_out;

    static cudaStream_t s2 = nullptr;
    static cudaEvent_t evFork = nullptr, evW = nullptr, evJoin = nullptr;
    if (s2 == nullptr) {
        cudaStreamCreateWithFlags(&s2, cudaStreamNonBlocking);
        cudaEventCreateWithFlags(&evFork, cudaEventDisableTiming);
        cudaEventCreateWithFlags(&evW, cudaEventDisableTiming);
        cudaEventCreateWithFlags(&evJoin, cudaEventDisableTiming);
        cudaFuncSetAttribute(k_gemm1_tc, cudaFuncAttributeMaxDynamicSharedMemorySize, SMEM_TOT);
    }

    const int TB = 256;
    int eg = (GE + TB - 1) / TB;

    cudaEventRecord(evFork, 0);
    cudaStreamWaitEvent(s2, evFork, 0);
    k_zero_wconv<<<NCHUNK, TB, 0, s2>>>(W1);      // #1
    cudaEventRecord(evW, s2);
    k_hist<<<eg, TB, 0, s2>>>(ei);                // #2
    k_scan<<<NCHUNK, TB, 0, s2>>>();              // #3
    cudaStreamWaitEvent(0, evW, 0);
    k_gemm1_tc<<<GM1_GRID, TB, SMEM_TOT>>>(x, att_s1, att_d1);   // #4 (main)
    k_scatter<<<eg, TB, 0, s2>>>(ei);             // #5 (side)
    cudaEventRecord(evJoin, s2);
    cudaStreamWaitEvent(0, evJoin, 0);

    k_agg1<<<NB8, TB>>>(b1, mask, W2, att_s2, att_d2);   // #6
    k_agg2<<<NB8, TB>>>(b2, out);                        // #7 (final fused)
}

// round 16
// speedup vs baseline: 1.0512x; 1.0222x over previous
#include <cuda_runtime.h>
#include <cuda_bf16.h>
#include <cuda_fp16.h>
#include <math.h>
#include <stdint.h>

#define GN 100000
#define GE 1600000
#define GF 500
#define GH1 8
#define GHC 64
#define GC2 7
#define NEG 0.2f
#define NCHUNK 391        // ceil(GN/256)
#define NB8 3125          // GN*8/256 exact
#define GM1_GRID 782      // ceil(GN/128)

// ---------------- scratch ----------------
__device__ int   g_deg[GN];
__device__ int   g_off[GN + 1];
__device__ int   g_cursor[GN];
__device__ int   g_csr[GE];
__device__ int   g_aggr[NCHUNK];
__device__ int   g_scan_count;
__device__ int   g_done;
__device__ __half g_h1h[GN * GHC];        // layer1 features, fp16 (message payload)
__device__ float g_as1[GN * GH1];
__device__ float g_ad1[GN * GH1];
__device__ __half g_zh[GN * 8];           // layer2 features, fp16
__device__ float g_as2[GN];
__device__ float g_ad2[GN];
__device__ float g_calib[NB8];
__device__ __nv_bfloat16 g_wh[64 * 512];  // W transposed [n][kk], hi, zero-padded
__device__ __nv_bfloat16 g_wl[64 * 512];  // lo

__device__ __forceinline__ float lrelu(float v) { return v > 0.f ? v : NEG * v; }

// FMA-only exp (keeps MUFU free; rel err ~1e-7, valid |x| < 80)
__device__ __forceinline__ float fexp(float x) {
    const float LOG2E = 1.4426950408889634f;
    float t = fmaf(x, LOG2E, 12582912.0f);
    int   ni = __float_as_int(t) - 0x4B400000;
    float n = t - 12582912.0f;
    float f = fmaf(x, LOG2E, -n);
    float p = 0.0013333558f;
    p = fmaf(p, f, 0.0096181291f);
    p = fmaf(p, f, 0.0555041087f);
    p = fmaf(p, f, 0.2402265069f);
    p = fmaf(p, f, 0.6931471806f);
    p = fmaf(p, f, 1.0f);
    return p * __int_as_float((ni + 127) << 23);
}

__device__ __forceinline__ uint32_t smem_u32(const void* p) {
    uint32_t a;
    asm("{ .reg .u64 t; cvta.to.shared.u64 t, %1; cvt.u32.u64 %0, t; }" : "=r"(a) : "l"(p));
    return a;
}

// split float2 -> hi/lo bf16x2 words
__device__ __forceinline__ void cvt2(float2 v, uint32_t& h, uint32_t& l) {
    uint32_t hp;
    asm("cvt.rn.bf16x2.f32 %0, %1, %2;" : "=r"(hp) : "f"(v.y), "f"(v.x));
    float hx = __int_as_float(hp << 16);
    float hy = __int_as_float(hp & 0xFFFF0000u);
    float lx = v.x - hx, ly = v.y - hy;
    asm("cvt.rn.bf16x2.f32 %0, %1, %2;" : "=r"(l) : "f"(ly), "f"(lx));
    h = hp;
}

__device__ __forceinline__ void unpack8(uint4 pk, float* f) {
    const __half2* hp = (const __half2*)&pk;
#pragma unroll
    for (int i = 0; i < 4; i++) {
        float2 t = __half22float2(hp[i]);
        f[2 * i] = t.x;
        f[2 * i + 1] = t.y;
    }
}

// ---------------- CSR init + W pre-conversion (fused) ----------------
__global__ void k_zero_wconv(const float* __restrict__ W) {
    int i = blockIdx.x * blockDim.x + threadIdx.x;
    if (i < GN) g_deg[i] = 0;
    if (i == 0) { g_scan_count = 0; g_done = 0; }
    if (i < 64 * 512) {
        int n = i >> 9, kk = i & 511;
        float w = (kk < GF) ? W[(size_t)kk * 64 + n] : 0.f;
        __nv_bfloat16 h = __float2bfloat16(w);
        g_wh[i] = h;
        g_wl[i] = __float2bfloat16(w - __bfloat162float(h));
    }
}

__global__ void k_hist(const int* __restrict__ ei) {
    int e = blockIdx.x * blockDim.x + threadIdx.x;
    if (e < GE) atomicAdd(&g_deg[ei[GE + e]], 1);
}

// single-pass scan
__global__ void k_scan() {
    __shared__ int sh[256];
    int i = blockIdx.x * 256 + threadIdx.x;
    int v = (i < GN) ? g_deg[i] : 0;
    sh[threadIdx.x] = v;
    __syncthreads();
    for (int d = 1; d < 256; d <<= 1) {
        int t = (threadIdx.x >= d) ? sh[threadIdx.x - d] : 0;
        __syncthreads();
        sh[threadIdx.x] += t;
        __syncthreads();
    }
    int incl = sh[threadIdx.x];
    if (threadIdx.x == 255) {
        g_aggr[blockIdx.x] = incl;
        __threadfence();
        atomicAdd(&g_scan_count, 1);
    }
    if (threadIdx.x == 0) {
        while (atomicAdd(&g_scan_count, 0) < NCHUNK) { }
    }
    __syncthreads();
    int pre = 0;
    for (int b = threadIdx.x; b < blockIdx.x; b += 256) pre += __ldcg(&g_aggr[b]);
    __syncthreads();
    sh[threadIdx.x] = pre;
    __syncthreads();
    for (int d = 128; d > 0; d >>= 1) {
        if (threadIdx.x < d) sh[threadIdx.x] += sh[threadIdx.x + d];
        __syncthreads();
    }
    int o = sh[0] + incl - v;
    if (i < GN) { g_off[i] = o; g_cursor[i] = o; }
    if (i == 0) g_off[GN] = GE;
}

__global__ void k_scatter(const int* __restrict__ ei) {
    int e = blockIdx.x * blockDim.x + threadIdx.x;
    if (e < GE) {
        int dst = ei[GE + e];
        int pos = atomicAdd(&g_cursor[dst], 1);
        g_csr[pos] = ei[e];
    }
}

// ---------------- GEMM1: cp.async double-buffered A (raw fp32) + B; reg-convert A ----------------
#define SAW 36
#define BBUF_WORDS (64 * SAW)
#define B_BYTES (2 * 2 * BBUF_WORDS * 4)   // 36864
#define ASTR 72
#define ABUF (128 * ASTR)
#define OFF_RAWA B_BYTES
#define SMEM_TOT (B_BYTES + 2 * ABUF * 4)  // 110592

#define MMA_BF16S(c, a, b0v, b1v) \
    asm volatile("mma.sync.aligned.m16n8k16.row.col.f32.bf16.bf16.f32 " \
        "{%0,%1,%2,%3}, {%4,%5,%6,%7}, {%8,%9}, {%0,%1,%2,%3};" \
        : "+f"((c)[0]), "+f"((c)[1]), "+f"((c)[2]), "+f"((c)[3]) \
        : "r"((a)[0]), "r"((a)[1]), "r"((a)[2]), "r"((a)[3]), "r"(b0v), "r"(b1v))

#define LDSM4(r, addr) \
    asm volatile("ldmatrix.sync.aligned.m8n8.x4.shared.b16 {%0,%1,%2,%3}, [%4];" \
        : "=r"((r)[0]), "=r"((r)[1]), "=r"((r)[2]), "=r"((r)[3]) : "r"(addr))

__global__ __launch_bounds__(256, 2) void k_gemm1_tc(const float* __restrict__ x,
                                                     const float* __restrict__ att_s,
                                                     const float* __restrict__ att_d) {
    extern __shared__ char smem[];
    uint32_t* B32 = (uint32_t*)smem;
    float* rawA = (float*)(smem + OFF_RAWA);

    int tid = threadIdx.x, wid = tid >> 5, lid = tid & 31;
    int g = lid >> 2, tg = lid & 3;
    int brow = blockIdx.x * 128;

    int r0 = brow + wid * 16 + g;
    int r1 = r0 + 8;
    bool ok0 = r0 < GN, ok1 = r1 < GN;
    int rl0 = wid * 16 + g, rl1 = rl0 + 8;

    float acc[8][4] = {};

    auto prefetchB = [&](int st, int buf) {
        int k0 = st * 64;
        uint32_t* base = B32 + buf * 2 * BBUF_WORDS;
        for (int slot = tid; slot < 1024; slot += 256) {
            int part = slot >> 9, i = slot & 511;
            int n = i >> 3, c = i & 7;
            uint32_t dst = smem_u32(base + part * BBUF_WORDS + n * SAW + c * 4);
            const __nv_bfloat16* src = (part ? g_wl : g_wh) + n * 512 + k0 + c * 8;
            asm volatile("cp.async.cg.shared.global [%0], [%1], 16;" :: "r"(dst), "l"(src));
        }
    };

    auto prefetchA = [&](int st, int buf) {
        int k0 = st * 64;
        float* base = rawA + buf * ABUF;
        for (int slot = tid; slot < 2048; slot += 256) {
            int r = slot >> 4, f4 = slot & 15;
            int row = brow + r, k = k0 + f4 * 4;
            uint32_t dst = smem_u32(base + r * ASTR + f4 * 4);
            if (row < GN && k + 3 < GF) {
                const float* src = x + (size_t)row * GF + k;
                asm volatile("cp.async.cg.shared.global [%0], [%1], 16;" :: "r"(dst), "l"(src));
            } else {
                asm volatile("st.shared.v4.b32 [%0], {%1,%1,%1,%1};" :: "r"(dst), "r"(0) : "memory");
            }
        }
    };

    prefetchB(0, 0);
    prefetchA(0, 0);
    asm volatile("cp.async.commit_group;" ::: "memory");
    asm volatile("cp.async.wait_group 0;" ::: "memory");
    __syncthreads();

    for (int st = 0; st < 8; st++) {
        int buf = st & 1;
        if (st < 7) {
            prefetchB(st + 1, buf ^ 1);
            prefetchA(st + 1, buf ^ 1);
            asm volatile("cp.async.commit_group;" ::: "memory");
        }

        uint32_t* bh = B32 + buf * 2 * BBUF_WORDS;
        uint32_t* bl = bh + BBUF_WORDS;
        uint32_t bhA = smem_u32(bh + lid * SAW);
        uint32_t bhB = smem_u32(bh + (32 + lid) * SAW);
        uint32_t blA = smem_u32(bl + lid * SAW);
        uint32_t blB = smem_u32(bl + (32 + lid) * SAW);
        const float* aBase = rawA + buf * ABUF;

#pragma unroll
        for (int ks = 0; ks < 4; ks++) {
            int kl = ks * 16 + 2 * tg;
            float2 a00 = *(const float2*)(aBase + rl0 * ASTR + kl);
            float2 a10 = *(const float2*)(aBase + rl1 * ASTR + kl);
            float2 a01 = *(const float2*)(aBase + rl0 * ASTR + kl + 8);
            float2 a11 = *(const float2*)(aBase + rl1 * ASTR + kl + 8);
            uint32_t ah[4], al[4];
            cvt2(a00, ah[0], al[0]);
            cvt2(a10, ah[1], al[1]);
            cvt2(a01, ah[2], al[2]);
            cvt2(a11, ah[3], al[3]);

            uint32_t b0hA[4], b1hA[4], b0hB[4], b1hB[4];
            uint32_t b0lA[4], b1lA[4], b0lB[4], b1lB[4];
            LDSM4(b0hA, bhA + ks * 32);
            LDSM4(b1hA, bhA + ks * 32 + 16);
            LDSM4(b0hB, bhB + ks * 32);
            LDSM4(b1hB, bhB + ks * 32 + 16);
            LDSM4(b0lA, blA + ks * 32);
            LDSM4(b1lA, blA + ks * 32 + 16);
            LDSM4(b0lB, blB + ks * 32);
            LDSM4(b1lB, blB + ks * 32 + 16);

#pragma unroll
            for (int fn = 0; fn < 8; fn++) {
                uint32_t b0h = (fn < 4) ? b0hA[fn] : b0hB[fn - 4];
                uint32_t b1h = (fn < 4) ? b1hA[fn] : b1hB[fn - 4];
                uint32_t b0l = (fn < 4) ? b0lA[fn] : b0lB[fn - 4];
                uint32_t b1l = (fn < 4) ? b1lA[fn] : b1lB[fn - 4];
                MMA_BF16S(acc[fn], ah, b0h, b1h);
                MMA_BF16S(acc[fn], ah, b0l, b1l);
                MMA_BF16S(acc[fn], al, b0h, b1h);
            }
        }

        if (st < 7) {
            asm volatile("cp.async.wait_group 0;" ::: "memory");
            __syncthreads();
        }
    }

    // ---- epilogue: write h1 (fp16) + fused as1/ad1 (fp32, from exact acc)
    float as_c[8][2], ad_c[8][2];
#pragma unroll
    for (int fn = 0; fn < 8; fn++) {
        int col = fn * 8 + tg * 2;
        as_c[fn][0] = __ldg(&att_s[col]);     as_c[fn][1] = __ldg(&att_s[col + 1]);
        ad_c[fn][0] = __ldg(&att_d[col]);     ad_c[fn][1] = __ldg(&att_d[col + 1]);
    }
    float sh0[8], dh0[8], sh1[8], dh1[8];
#pragma unroll
    for (int fn = 0; fn < 8; fn++) {
        int col = fn * 8 + tg * 2;
        float c0 = acc[fn][0], c1 = acc[fn][1], c2 = acc[fn][2], c3 = acc[fn][3];
        if (ok0) *(__half2*)&g_h1h[(size_t)r0 * GHC + col] = __floats2half2_rn(c0, c1);
        if (ok1) *(__half2*)&g_h1h[(size_t)r1 * GHC + col] = __floats2half2_rn(c2, c3);
        sh0[fn] = c0 * as_c[fn][0] + c1 * as_c[fn][1];
        dh0[fn] = c0 * ad_c[fn][0] + c1 * ad_c[fn][1];
        sh1[fn] = c2 * as_c[fn][0] + c3 * as_c[fn][1];
        dh1[fn] = c2 * ad_c[fn][0] + c3 * ad_c[fn][1];
    }
#pragma unroll
    for (int w = 1; w < 4; w <<= 1)
#pragma unroll
        for (int fn = 0; fn < 8; fn++) {
            sh0[fn] += __shfl_xor_sync(0xffffffffu, sh0[fn], w, 4);
            dh0[fn] += __shfl_xor_sync(0xffffffffu, dh0[fn], w, 4);
            sh1[fn] += __shfl_xor_sync(0xffffffffu, sh1[fn], w, 4);
            dh1[fn] += __shfl_xor_sync(0xffffffffu, dh1[fn], w, 4);
        }
    if (tg == 0) {
#pragma unroll
        for (int fn = 0; fn < 8; fn++) {
            if (ok0) { g_as1[r0 * 8 + fn] = sh0[fn]; g_ad1[r0 * 8 + fn] = dh0[fn]; }
            if (ok1) { g_as1[r1 * 8 + fn] = sh1[fn]; g_ad1[r1 * 8 + fn] = dh1[fn]; }
        }
    }
}

// ---------------- layer-1 agg (thread-per-(node,head), 4x-batched gather) + fused GEMM2/alphas2 ----------------
__global__ __launch_bounds__(256) void k_agg1(const float* __restrict__ b1,
                                              const float* __restrict__ mask,
                                              const float* __restrict__ W2,
                                              const float* __restrict__ as2v,
                                              const float* __restrict__ ad2v) {
    __shared__ float sw[448], sas[7], sad[7];
    for (int i = threadIdx.x; i < 448; i += 256) sw[i] = W2[i];
    if (threadIdx.x < 7) { sas[threadIdx.x] = as2v[threadIdx.x]; sad[threadIdx.x] = ad2v[threadIdx.x]; }
    __syncthreads();

    int gid = blockIdx.x * 256 + threadIdx.x;   // GN*8 exact
    int node = gid >> 3, h = gid & 7;
    float adst = g_ad1[gid];
    float s = fexp(lrelu(g_as1[gid] + adst));     // self edge
    float f[8], ac[8];
    unpack8(*(const uint4*)(g_h1h + (size_t)node * GHC + h * 8), f);
#pragma unroll
    for (int c = 0; c < 8; c++) ac[c] = s * f[c];
    int beg = g_off[node], end = g_off[node + 1];
    int i = beg;
    // 4x batched: all independent loads issued before any dependent math
    for (; i + 4 <= end; i += 4) {
        int s0 = __ldg(&g_csr[i]);
        int s1 = __ldg(&g_csr[i + 1]);
        int s2 = __ldg(&g_csr[i + 2]);
        int s3 = __ldg(&g_csr[i + 3]);
        float e0 = __ldg(&g_as1[s0 * GH1 + h]);
        float e1 = __ldg(&g_as1[s1 * GH1 + h]);
        float e2 = __ldg(&g_as1[s2 * GH1 + h]);
        float e3 = __ldg(&g_as1[s3 * GH1 + h]);
        uint4 p0 = __ldg((const uint4*)(g_h1h + (size_t)s0 * GHC + h * 8));
        uint4 p1 = __ldg((const uint4*)(g_h1h + (size_t)s1 * GHC + h * 8));
        uint4 p2 = __ldg((const uint4*)(g_h1h + (size_t)s2 * GHC + h * 8));
        uint4 p3 = __ldg((const uint4*)(g_h1h + (size_t)s3 * GHC + h * 8));
        float w0 = fexp(lrelu(e0 + adst));
        float w1 = fexp(lrelu(e1 + adst));
        float w2 = fexp(lrelu(e2 + adst));
        float w3 = fexp(lrelu(e3 + adst));
        s += w0 + w1 + w2 + w3;
        float f0[8], f1[8], f2[8], f3[8];
        unpack8(p0, f0); unpack8(p1, f1); unpack8(p2, f2); unpack8(p3, f3);
#pragma unroll
        for (int c = 0; c < 8; c++)
            ac[c] += w0 * f0[c] + w1 * f1[c] + w2 * f2[c] + w3 * f3[c];
    }
    for (; i < end; i++) {
        int src = __ldg(&g_csr[i]);
        float w = fexp(lrelu(__ldg(&g_as1[src * GH1 + h]) + adst));
        uint4 pk = __ldg((const uint4*)(g_h1h + (size_t)src * GHC + h * 8));
        unpack8(pk, f);
        s += w;
#pragma unroll
        for (int c = 0; c < 8; c++) ac[c] += w * f[c];
    }
    float inv = 1.0f / (s + 1e-16f);
    int base = node * GHC + h * 8;
    float z[7] = {};
#pragma unroll
    for (int c = 0; c < 8; c++) {
        float v = ac[c] * inv + b1[h * 8 + c];
        float hv = fmaxf(v, 0.f) * mask[base + c];
        const float* wr = &sw[(h * 8 + c) * 7];
#pragma unroll
        for (int j = 0; j < 7; j++) z[j] += hv * wr[j];
    }
#pragma unroll
    for (int w = 1; w < 8; w <<= 1)
#pragma unroll
        for (int j = 0; j < 7; j++) z[j] += __shfl_xor_sync(0xffffffffu, z[j], w, 8);
    if (h == 0) {
        float as = 0.f, ad = 0.f;
        __half zh[8];
#pragma unroll
        for (int j = 0; j < 7; j++) {
            as += z[j] * sas[j];
            ad += z[j] * sad[j];
            zh[j] = __float2half(z[j]);
        }
        zh[7] = __float2half(0.f);
        *(uint4*)(g_zh + (size_t)node * 8) = *(uint4*)zh;
        g_as2[node] = as;
        g_ad2[node] = ad;
    }
}

// ---------------- layer-2 agg (8 lanes/node, 4x-batched) + epilogue + fused final ----------------
__global__ __launch_bounds__(256) void k_agg2(const float* __restrict__ b2,
                                              float* __restrict__ out) {
    int gid = blockIdx.x * 256 + threadIdx.x;    // GN*8 exact
    int node = gid >> 3, c = gid & 7;
    float adst = g_ad2[node];
    float s = fexp(lrelu(g_as2[node] + adst));
    float acc = s * __half2float(g_zh[(size_t)node * 8 + c]);
    int beg = g_off[node], end = g_off[node + 1];
    int i = beg;
    for (; i + 4 <= end; i += 4) {
        int s0 = __ldg(&g_csr[i]);
        int s1 = __ldg(&g_csr[i + 1]);
        int s2 = __ldg(&g_csr[i + 2]);
        int s3 = __ldg(&g_csr[i + 3]);
        float e0 = __ldg(&g_as2[s0]);
        float e1 = __ldg(&g_as2[s1]);
        float e2 = __ldg(&g_as2[s2]);
        float e3 = __ldg(&g_as2[s3]);
        float z0 = __half2float(__ldg(&g_zh[(size_t)s0 * 8 + c]));
        float z1 = __half2float(__ldg(&g_zh[(size_t)s1 * 8 + c]));
        float z2 = __half2float(__ldg(&g_zh[(size_t)s2 * 8 + c]));
        float z3 = __half2float(__ldg(&g_zh[(size_t)s3 * 8 + c]));
        float w0 = fexp(lrelu(e0 + adst));
        float w1 = fexp(lrelu(e1 + adst));
        float w2 = fexp(lrelu(e2 + adst));
        float w3 = fexp(lrelu(e3 + adst));
        s += w0 + w1 + w2 + w3;
        acc += w0 * z0 + w1 * z1 + w2 * z2 + w3 * z3;
    }
    for (; i < end; i++) {
        int src = __ldg(&g_csr[i]);
        float w = fexp(lrelu(__ldg(&g_as2[src]) + adst));
        s += w;
        acc += w * __half2float(__ldg(&g_zh[(size_t)src * 8 + c]));
    }
    float xo = acc / (s + 1e-16f) + ((c < 7) ? b2[c] : 0.f);
    float xv = (c < 7) ? xo : -1e30f;
    float mx = xv;
#pragma unroll
    for (int w = 1; w < 8; w <<= 1) mx = fmaxf(mx, __shfl_xor_sync(0xffffffffu, mx, w, 8));
    float e = (c < 7) ? fexp(xo - mx) : 0.f;
    float sum = e;
#pragma unroll
    for (int w = 1; w < 8; w <<= 1) sum += __shfl_xor_sync(0xffffffffu, sum, w, 8);
    float lse = __logf(sum);
    float p = e / sum;
    if (c < 7) {
        out[(size_t)node * 7 + c] = xo - mx - lse;          // log_softmax
        out[700001 + (size_t)node * 7 + c] = p;             // softmax
    }
    float p1 = -1.f, p2 = -1.f;
#pragma unroll
    for (int j = 0; j < 7; j++) {
        float pj = __shfl_sync(0xffffffffu, p, j, 8);
        if (pj > p1) { p2 = p1; p1 = pj; }
        else if (pj > p2) { p2 = pj; }
    }
    float calib = (c == 0) ? (1.0f - p1 + p2) : 0.f;
    __shared__ float red[256];
    __shared__ int lastFlag;
    red[threadIdx.x] = calib;
    __syncthreads();
    for (int d = 128; d > 0; d >>= 1) {
        if (threadIdx.x < d) red[threadIdx.x] += red[threadIdx.x + d];
        __syncthreads();
    }
    if (threadIdx.x == 0) {
        g_calib[blockIdx.x] = red[0];
        __threadfence();
        int t = atomicAdd(&g_done, 1);
        lastFlag = (t == NB8 - 1);
    }
    __syncthreads();
    if (lastFlag) {           // last block: deterministic fixed-order reduction
        float sum2 = 0.f;
        for (int i2 = threadIdx.x; i2 < NB8; i2 += 256) sum2 += __ldcg(&g_calib[i2]);
        red[threadIdx.x] = sum2;
        __syncthreads();
        for (int d = 128; d > 0; d >>= 1) {
            if (threadIdx.x < d) red[threadIdx.x] += red[threadIdx.x + d];
            __syncthreads();
        }
        if (threadIdx.x == 0) out[700000] = red[0] / (float)GN;
    }
}

// ---------------- launch: gemm1 stays 4th submitted kernel (ncu window) ----------------
extern "C" void kernel_launch(void* const* d_in, const int* in_sizes, int n_in,
                              void* d_out, int out_size) {
    const float* x        = (const float*)d_in[0];
    const int*   ei       = (const int*)d_in[1];
    const float* mask     = (const float*)d_in[2];
    const float* W1       = (const float*)d_in[3];
    const float* att_s1   = (const float*)d_in[4];
    const float* att_d1   = (const float*)d_in[5];
    const float* b1       = (const float*)d_in[6];
    const float* W2       = (const float*)d_in[7];
    const float* att_s2   = (const float*)d_in[8];
    const float* att_d2   = (const float*)d_in[9];
    const float* b2       = (const float*)d_in[10];
    float* out = (float*)d_out;

    static cudaStream_t s2 = nullptr;
    static cudaEvent_t evFork = nullptr, evW = nullptr, evJoin = nullptr;
    if (s2 == nullptr) {
        cudaStreamCreateWithFlags(&s2, cudaStreamNonBlocking);
        cudaEventCreateWithFlags(&evFork, cudaEventDisableTiming);
        cudaEventCreateWithFlags(&evW, cudaEventDisableTiming);
        cudaEventCreateWithFlags(&evJoin, cudaEventDisableTiming);
        cudaFuncSetAttribute(k_gemm1_tc, cudaFuncAttributeMaxDynamicSharedMemorySize, SMEM_TOT);
    }

    const int TB = 256;
    int eg = (GE + TB - 1) / TB;

    cudaEventRecord(evFork, 0);
    cudaStreamWaitEvent(s2, evFork, 0);
    k_zero_wconv<<<NCHUNK, TB, 0, s2>>>(W1);      // #1
    cudaEventRecord(evW, s2);
    k_hist<<<eg, TB, 0, s2>>>(ei);                // #2
    k_scan<<<NCHUNK, TB, 0, s2>>>();              // #3
    cudaStreamWaitEvent(0, evW, 0);
    k_gemm1_tc<<<GM1_GRID, TB, SMEM_TOT>>>(x, att_s1, att_d1);   // #4 (main)
    k_scatter<<<eg, TB, 0, s2>>>(ei);             // #5 (side)
    cudaEventRecord(evJoin, s2);
    cudaStreamWaitEvent(0, evJoin, 0);

    k_agg1<<<NB8, TB>>>(b1, mask, W2, att_s2, att_d2);   // #6
    k_agg2<<<NB8, TB>>>(b2, out);                        // #7 (final fused)
}

// round 17
// speedup vs baseline: 1.0932x; 1.0400x over previous
#include <cuda_runtime.h>
#include <cuda_bf16.h>
#include <cuda_fp16.h>
#include <math.h>
#include <stdint.h>

#define GN 100000
#define GE 1600000
#define GF 500
#define GH1 8
#define GHC 64
#define GC2 7
#define NEG 0.2f
#define NCHUNK 391        // ceil(GN/256)
#define NB8 3125          // GN*8/256 exact
#define GM1_GRID 782      // ceil(GN/128)

// ---------------- scratch ----------------
__device__ int   g_deg[GN];
__device__ int   g_off[GN + 1];
__device__ int   g_cursor[GN];
__device__ int   g_csr[GE];
__device__ int   g_aggr[NCHUNK];
__device__ int   g_scan_count;
__device__ int   g_done;
__device__ __half g_h1h[GN * GHC];        // layer1 features, fp16 (message payload)
__device__ float g_as1[GN * GH1];
__device__ float g_ad1[GN * GH1];
__device__ __half g_zh[GN * 8];           // layer2 features, fp16
__device__ float g_as2[GN];
__device__ float g_ad2[GN];
__device__ float g_calib[NB8];
__device__ __nv_bfloat16 g_wh[64 * 512];  // W transposed [n][kk], hi, zero-padded
__device__ __nv_bfloat16 g_wl[64 * 512];  // lo

__device__ __forceinline__ float lrelu(float v) { return v > 0.f ? v : NEG * v; }

// FMA-only exp (keeps MUFU free; rel err ~1e-7, valid |x| < 80)
__device__ __forceinline__ float fexp(float x) {
    const float LOG2E = 1.4426950408889634f;
    float t = fmaf(x, LOG2E, 12582912.0f);
    int   ni = __float_as_int(t) - 0x4B400000;
    float n = t - 12582912.0f;
    float f = fmaf(x, LOG2E, -n);
    float p = 0.0013333558f;
    p = fmaf(p, f, 0.0096181291f);
    p = fmaf(p, f, 0.0555041087f);
    p = fmaf(p, f, 0.2402265069f);
    p = fmaf(p, f, 0.6931471806f);
    p = fmaf(p, f, 1.0f);
    return p * __int_as_float((ni + 127) << 23);
}

__device__ __forceinline__ uint32_t smem_u32(const void* p) {
    uint32_t a;
    asm("{ .reg .u64 t; cvta.to.shared.u64 t, %1; cvt.u32.u64 %0, t; }" : "=r"(a) : "l"(p));
    return a;
}

// split float2 -> hi/lo bf16x2 words
__device__ __forceinline__ void cvt2(float2 v, uint32_t& h, uint32_t& l) {
    uint32_t hp;
    asm("cvt.rn.bf16x2.f32 %0, %1, %2;" : "=r"(hp) : "f"(v.y), "f"(v.x));
    float hx = __int_as_float(hp << 16);
    float hy = __int_as_float(hp & 0xFFFF0000u);
    float lx = v.x - hx, ly = v.y - hy;
    asm("cvt.rn.bf16x2.f32 %0, %1, %2;" : "=r"(l) : "f"(ly), "f"(lx));
    h = hp;
}

__device__ __forceinline__ void unpack8(uint4 pk, float* f) {
    const __half2* hp = (const __half2*)&pk;
#pragma unroll
    for (int i = 0; i < 4; i++) {
        float2 t = __half22float2(hp[i]);
        f[2 * i] = t.x;
        f[2 * i + 1] = t.y;
    }
}

// ---------------- CSR init + W pre-conversion (fused) ----------------
__global__ void k_zero_wconv(const float* __restrict__ W) {
    int i = blockIdx.x * blockDim.x + threadIdx.x;
    if (i < GN) g_deg[i] = 0;
    if (i == 0) { g_scan_count = 0; g_done = 0; }
    if (i < 64 * 512) {
        int n = i >> 9, kk = i & 511;
        float w = (kk < GF) ? W[(size_t)kk * 64 + n] : 0.f;
        __nv_bfloat16 h = __float2bfloat16(w);
        g_wh[i] = h;
        g_wl[i] = __float2bfloat16(w - __bfloat162float(h));
    }
}

__global__ void k_hist(const int* __restrict__ ei) {
    int e = blockIdx.x * blockDim.x + threadIdx.x;
    if (e < GE) atomicAdd(&g_deg[ei[GE + e]], 1);
}

// single-pass scan
__global__ void k_scan() {
    __shared__ int sh[256];
    int i = blockIdx.x * 256 + threadIdx.x;
    int v = (i < GN) ? g_deg[i] : 0;
    sh[threadIdx.x] = v;
    __syncthreads();
    for (int d = 1; d < 256; d <<= 1) {
        int t = (threadIdx.x >= d) ? sh[threadIdx.x - d] : 0;
        __syncthreads();
        sh[threadIdx.x] += t;
        __syncthreads();
    }
    int incl = sh[threadIdx.x];
    if (threadIdx.x == 255) {
        g_aggr[blockIdx.x] = incl;
        __threadfence();
        atomicAdd(&g_scan_count, 1);
    }
    if (threadIdx.x == 0) {
        while (atomicAdd(&g_scan_count, 0) < NCHUNK) { }
    }
    __syncthreads();
    int pre = 0;
    for (int b = threadIdx.x; b < blockIdx.x; b += 256) pre += __ldcg(&g_aggr[b]);
    __syncthreads();
    sh[threadIdx.x] = pre;
    __syncthreads();
    for (int d = 128; d > 0; d >>= 1) {
        if (threadIdx.x < d) sh[threadIdx.x] += sh[threadIdx.x + d];
        __syncthreads();
    }
    int o = sh[0] + incl - v;
    if (i < GN) { g_off[i] = o; g_cursor[i] = o; }
    if (i == 0) g_off[GN] = GE;
}

__global__ void k_scatter(const int* __restrict__ ei) {
    int e = blockIdx.x * blockDim.x + threadIdx.x;
    if (e < GE) {
        int dst = ei[GE + e];
        int pos = atomicAdd(&g_cursor[dst], 1);
        g_csr[pos] = ei[e];
    }
}

// ---------------- GEMM1: K-stage 32, 3 CTAs/SM, cp.async double-buffered ----------------
#define NST 16                         // 16 stages of K=32
#define SAW 20                         // B row stride in words (16 data + 4 pad)
#define BBUF_WORDS (64 * SAW)          // 1280 words per part
#define B_BYTES (2 * 2 * BBUF_WORDS * 4)   // 20480
#define ASTR 36                        // rawA row stride in floats (32 data + 4 pad)
#define ABUF (128 * ASTR)              // 4608 floats per buffer
#define OFF_RAWA B_BYTES
#define SMEM_TOT (B_BYTES + 2 * ABUF * 4)  // 20480 + 36864 = 57344

#define MMA_BF16S(c, a, b0v, b1v) \
    asm volatile("mma.sync.aligned.m16n8k16.row.col.f32.bf16.bf16.f32 " \
        "{%0,%1,%2,%3}, {%4,%5,%6,%7}, {%8,%9}, {%0,%1,%2,%3};" \
        : "+f"((c)[0]), "+f"((c)[1]), "+f"((c)[2]), "+f"((c)[3]) \
        : "r"((a)[0]), "r"((a)[1]), "r"((a)[2]), "r"((a)[3]), "r"(b0v), "r"(b1v))

#define LDSM4(r, addr) \
    asm volatile("ldmatrix.sync.aligned.m8n8.x4.shared.b16 {%0,%1,%2,%3}, [%4];" \
        : "=r"((r)[0]), "=r"((r)[1]), "=r"((r)[2]), "=r"((r)[3]) : "r"(addr))

__global__ __launch_bounds__(256, 3) void k_gemm1_tc(const float* __restrict__ x,
                                                     const float* __restrict__ att_s,
                                                     const float* __restrict__ att_d) {
    extern __shared__ char smem[];
    uint32_t* B32 = (uint32_t*)smem;
    float* rawA = (float*)(smem + OFF_RAWA);

    int tid = threadIdx.x, wid = tid >> 5, lid = tid & 31;
    int g = lid >> 2, tg = lid & 3;
    int brow = blockIdx.x * 128;

    int r0 = brow + wid * 16 + g;
    int r1 = r0 + 8;
    bool ok0 = r0 < GN, ok1 = r1 < GN;
    int rl0 = wid * 16 + g, rl1 = rl0 + 8;

    float acc[8][4] = {};

    auto prefetchB = [&](int st, int buf) {
        int k0 = st * 32;
        uint32_t* base = B32 + buf * 2 * BBUF_WORDS;
        for (int slot = tid; slot < 512; slot += 256) {
            int part = slot >> 8, i = slot & 255;
            int n = i >> 2, c = i & 3;
            uint32_t dst = smem_u32(base + part * BBUF_WORDS + n * SAW + c * 4);
            const __nv_bfloat16* src = (part ? g_wl : g_wh) + n * 512 + k0 + c * 8;
            asm volatile("cp.async.cg.shared.global [%0], [%1], 16;" :: "r"(dst), "l"(src));
        }
    };

    auto prefetchA = [&](int st, int buf) {
        int k0 = st * 32;
        float* base = rawA + buf * ABUF;
        for (int slot = tid; slot < 1024; slot += 256) {
            int r = slot >> 3, f4 = slot & 7;
            int row = brow + r, k = k0 + f4 * 4;
            uint32_t dst = smem_u32(base + r * ASTR + f4 * 4);
            if (row < GN && k + 3 < GF) {
                const float* src = x + (size_t)row * GF + k;
                asm volatile("cp.async.cg.shared.global [%0], [%1], 16;" :: "r"(dst), "l"(src));
            } else {
                asm volatile("st.shared.v4.b32 [%0], {%1,%1,%1,%1};" :: "r"(dst), "r"(0) : "memory");
            }
        }
    };

    prefetchB(0, 0);
    prefetchA(0, 0);
    asm volatile("cp.async.commit_group;" ::: "memory");
    asm volatile("cp.async.wait_group 0;" ::: "memory");
    __syncthreads();

    for (int st = 0; st < NST; st++) {
        int buf = st & 1;
        if (st < NST - 1) {
            prefetchB(st + 1, buf ^ 1);
            prefetchA(st + 1, buf ^ 1);
            asm volatile("cp.async.commit_group;" ::: "memory");
        }

        uint32_t* bh = B32 + buf * 2 * BBUF_WORDS;
        uint32_t* bl = bh + BBUF_WORDS;
        uint32_t bhA = smem_u32(bh + lid * SAW);
        uint32_t bhB = smem_u32(bh + (32 + lid) * SAW);
        uint32_t blA = smem_u32(bl + lid * SAW);
        uint32_t blB = smem_u32(bl + (32 + lid) * SAW);
        const float* aBase = rawA + buf * ABUF;

#pragma unroll
        for (int ks = 0; ks < 2; ks++) {
            int kl = ks * 16 + 2 * tg;
            float2 a00 = *(const float2*)(aBase + rl0 * ASTR + kl);
            float2 a10 = *(const float2*)(aBase + rl1 * ASTR + kl);
            float2 a01 = *(const float2*)(aBase + rl0 * ASTR + kl + 8);
            float2 a11 = *(const float2*)(aBase + rl1 * ASTR + kl + 8);
            uint32_t ah[4], al[4];
            cvt2(a00, ah[0], al[0]);
            cvt2(a10, ah[1], al[1]);
            cvt2(a01, ah[2], al[2]);
            cvt2(a11, ah[3], al[3]);

            uint32_t b0hA[4], b1hA[4], b0hB[4], b1hB[4];
            uint32_t b0lA[4], b1lA[4], b0lB[4], b1lB[4];
            LDSM4(b0hA, bhA + ks * 32);
            LDSM4(b1hA, bhA + ks * 32 + 16);
            LDSM4(b0hB, bhB + ks * 32);
            LDSM4(b1hB, bhB + ks * 32 + 16);
            LDSM4(b0lA, blA + ks * 32);
            LDSM4(b1lA, blA + ks * 32 + 16);
            LDSM4(b0lB, blB + ks * 32);
            LDSM4(b1lB, blB + ks * 32 + 16);

#pragma unroll
            for (int fn = 0; fn < 8; fn++) {
                uint32_t b0h = (fn < 4) ? b0hA[fn] : b0hB[fn - 4];
                uint32_t b1h = (fn < 4) ? b1hA[fn] : b1hB[fn - 4];
                uint32_t b0l = (fn < 4) ? b0lA[fn] : b0lB[fn - 4];
                uint32_t b1l = (fn < 4) ? b1lA[fn] : b1lB[fn - 4];
                MMA_BF16S(acc[fn], ah, b0h, b1h);
                MMA_BF16S(acc[fn], ah, b0l, b1l);
                MMA_BF16S(acc[fn], al, b0h, b1h);
            }
        }

        if (st < NST - 1) {
            asm volatile("cp.async.wait_group 0;" ::: "memory");
            __syncthreads();
        }
    }

    // ---- epilogue: write h1 (fp16) + fused as1/ad1 (fp32, from exact acc)
    float as_c[8][2], ad_c[8][2];
#pragma unroll
    for (int fn = 0; fn < 8; fn++) {
        int col = fn * 8 + tg * 2;
        as_c[fn][0] = __ldg(&att_s[col]);     as_c[fn][1] = __ldg(&att_s[col + 1]);
        ad_c[fn][0] = __ldg(&att_d[col]);     ad_c[fn][1] = __ldg(&att_d[col + 1]);
    }
    float sh0[8], dh0[8], sh1[8], dh1[8];
#pragma unroll
    for (int fn = 0; fn < 8; fn++) {
        int col = fn * 8 + tg * 2;
        float c0 = acc[fn][0], c1 = acc[fn][1], c2 = acc[fn][2], c3 = acc[fn][3];
        if (ok0) *(__half2*)&g_h1h[(size_t)r0 * GHC + col] = __floats2half2_rn(c0, c1);
        if (ok1) *(__half2*)&g_h1h[(size_t)r1 * GHC + col] = __floats2half2_rn(c2, c3);
        sh0[fn] = c0 * as_c[fn][0] + c1 * as_c[fn][1];
        dh0[fn] = c0 * ad_c[fn][0] + c1 * ad_c[fn][1];
        sh1[fn] = c2 * as_c[fn][0] + c3 * as_c[fn][1];
        dh1[fn] = c2 * ad_c[fn][0] + c3 * ad_c[fn][1];
    }
#pragma unroll
    for (int w = 1; w < 4; w <<= 1)
#pragma unroll
        for (int fn = 0; fn < 8; fn++) {
            sh0[fn] += __shfl_xor_sync(0xffffffffu, sh0[fn], w, 4);
            dh0[fn] += __shfl_xor_sync(0xffffffffu, dh0[fn], w, 4);
            sh1[fn] += __shfl_xor_sync(0xffffffffu, sh1[fn], w, 4);
            dh1[fn] += __shfl_xor_sync(0xffffffffu, dh1[fn], w, 4);
        }
    if (tg == 0) {
#pragma unroll
        for (int fn = 0; fn < 8; fn++) {
            if (ok0) { g_as1[r0 * 8 + fn] = sh0[fn]; g_ad1[r0 * 8 + fn] = dh0[fn]; }
            if (ok1) { g_as1[r1 * 8 + fn] = sh1[fn]; g_ad1[r1 * 8 + fn] = dh1[fn]; }
        }
    }
}

// ---------------- layer-1 agg (thread-per-(node,head), 4x-batched gather) + fused GEMM2/alphas2 ----------------
__global__ __launch_bounds__(256) void k_agg1(const float* __restrict__ b1,
                                              const float* __restrict__ mask,
                                              const float* __restrict__ W2,
                                              const float* __restrict__ as2v,
                                              const float* __restrict__ ad2v) {
    __shared__ float sw[448], sas[7], sad[7];
    for (int i = threadIdx.x; i < 448; i += 256) sw[i] = W2[i];
    if (threadIdx.x < 7) { sas[threadIdx.x] = as2v[threadIdx.x]; sad[threadIdx.x] = ad2v[threadIdx.x]; }
    __syncthreads();

    int gid = blockIdx.x * 256 + threadIdx.x;   // GN*8 exact
    int node = gid >> 3, h = gid & 7;
    float adst = g_ad1[gid];
    float s = fexp(lrelu(g_as1[gid] + adst));     // self edge
    float f[8], ac[8];
    unpack8(*(const uint4*)(g_h1h + (size_t)node * GHC + h * 8), f);
#pragma unroll
    for (int c = 0; c < 8; c++) ac[c] = s * f[c];
    int beg = g_off[node], end = g_off[node + 1];
    int i = beg;
    for (; i + 4 <= end; i += 4) {
        int s0 = __ldg(&g_csr[i]);
        int s1 = __ldg(&g_csr[i + 1]);
        int s2 = __ldg(&g_csr[i + 2]);
        int s3 = __ldg(&g_csr[i + 3]);
        float e0 = __ldg(&g_as1[s0 * GH1 + h]);
        float e1 = __ldg(&g_as1[s1 * GH1 + h]);
        float e2 = __ldg(&g_as1[s2 * GH1 + h]);
        float e3 = __ldg(&g_as1[s3 * GH1 + h]);
        uint4 p0 = __ldg((const uint4*)(g_h1h + (size_t)s0 * GHC + h * 8));
        uint4 p1 = __ldg((const uint4*)(g_h1h + (size_t)s1 * GHC + h * 8));
        uint4 p2 = __ldg((const uint4*)(g_h1h + (size_t)s2 * GHC + h * 8));
        uint4 p3 = __ldg((const uint4*)(g_h1h + (size_t)s3 * GHC + h * 8));
        float w0 = fexp(lrelu(e0 + adst));
        float w1 = fexp(lrelu(e1 + adst));
        float w2 = fexp(lrelu(e2 + adst));
        float w3 = fexp(lrelu(e3 + adst));
        s += w0 + w1 + w2 + w3;
        float f0[8], f1[8], f2[8], f3[8];
        unpack8(p0, f0); unpack8(p1, f1); unpack8(p2, f2); unpack8(p3, f3);
#pragma unroll
        for (int c = 0; c < 8; c++)
            ac[c] += w0 * f0[c] + w1 * f1[c] + w2 * f2[c] + w3 * f3[c];
    }
    for (; i < end; i++) {
        int src = __ldg(&g_csr[i]);
        float w = fexp(lrelu(__ldg(&g_as1[src * GH1 + h]) + adst));
        uint4 pk = __ldg((const uint4*)(g_h1h + (size_t)src * GHC + h * 8));
        unpack8(pk, f);
        s += w;
#pragma unroll
        for (int c = 0; c < 8; c++) ac[c] += w * f[c];
    }
    float inv = 1.0f / (s + 1e-16f);
    int base = node * GHC + h * 8;
    float z[7] = {};
#pragma unroll
    for (int c = 0; c < 8; c++) {
        float v = ac[c] * inv + b1[h * 8 + c];
        float hv = fmaxf(v, 0.f) * mask[base + c];
        const float* wr = &sw[(h * 8 + c) * 7];
#pragma unroll
        for (int j = 0; j < 7; j++) z[j] += hv * wr[j];
    }
#pragma unroll
    for (int w = 1; w < 8; w <<= 1)
#pragma unroll
        for (int j = 0; j < 7; j++) z[j] += __shfl_xor_sync(0xffffffffu, z[j], w, 8);
    if (h == 0) {
        float as = 0.f, ad = 0.f;
        __half zh[8];
#pragma unroll
        for (int j = 0; j < 7; j++) {
            as += z[j] * sas[j];
            ad += z[j] * sad[j];
            zh[j] = __float2half(z[j]);
        }
        zh[7] = __float2half(0.f);
        *(uint4*)(g_zh + (size_t)node * 8) = *(uint4*)zh;
        g_as2[node] = as;
        g_ad2[node] = ad;
    }
}

// ---------------- layer-2 agg (8 lanes/node, 4x-batched) + epilogue + fused final ----------------
__global__ __launch_bounds__(256) void k_agg2(const float* __restrict__ b2,
                                              float* __restrict__ out) {
    int gid = blockIdx.x * 256 + threadIdx.x;    // GN*8 exact
    int node = gid >> 3, c = gid & 7;
    float adst = g_ad2[node];
    float s = fexp(lrelu(g_as2[node] + adst));
    float acc = s * __half2float(g_zh[(size_t)node * 8 + c]);
    int beg = g_off[node], end = g_off[node + 1];
    int i = beg;
    for (; i + 4 <= end; i += 4) {
        int s0 = __ldg(&g_csr[i]);
        int s1 = __ldg(&g_csr[i + 1]);
        int s2 = __ldg(&g_csr[i + 2]);
        int s3 = __ldg(&g_csr[i + 3]);
        float e0 = __ldg(&g_as2[s0]);
        float e1 = __ldg(&g_as2[s1]);
        float e2 = __ldg(&g_as2[s2]);
        float e3 = __ldg(&g_as2[s3]);
        float z0 = __half2float(__ldg(&g_zh[(size_t)s0 * 8 + c]));
        float z1 = __half2float(__ldg(&g_zh[(size_t)s1 * 8 + c]));
        float z2 = __half2float(__ldg(&g_zh[(size_t)s2 * 8 + c]));
        float z3 = __half2float(__ldg(&g_zh[(size_t)s3 * 8 + c]));
        float w0 = fexp(lrelu(e0 + adst));
        float w1 = fexp(lrelu(e1 + adst));
        float w2 = fexp(lrelu(e2 + adst));
        float w3 = fexp(lrelu(e3 + adst));
        s += w0 + w1 + w2 + w3;
        acc += w0 * z0 + w1 * z1 + w2 * z2 + w3 * z3;
    }
    for (; i < end; i++) {
        int src = __ldg(&g_csr[i]);
        float w = fexp(lrelu(__ldg(&g_as2[src]) + adst));
        s += w;
        acc += w * __half2float(__ldg(&g_zh[(size_t)src * 8 + c]));
    }
    float xo = acc / (s + 1e-16f) + ((c < 7) ? b2[c] : 0.f);
    float xv = (c < 7) ? xo : -1e30f;
    float mx = xv;
#pragma unroll
    for (int w = 1; w < 8; w <<= 1) mx = fmaxf(mx, __shfl_xor_sync(0xffffffffu, mx, w, 8));
    float e = (c < 7) ? fexp(xo - mx) : 0.f;
    float sum = e;
#pragma unroll
    for (int w = 1; w < 8; w <<= 1) sum += __shfl_xor_sync(0xffffffffu, sum, w, 8);
    float lse = __logf(sum);
    float p = e / sum;
    if (c < 7) {
        out[(size_t)node * 7 + c] = xo - mx - lse;          // log_softmax
        out[700001 + (size_t)node * 7 + c] = p;             // softmax
    }
    float p1 = -1.f, p2 = -1.f;
#pragma unroll
    for (int j = 0; j < 7; j++) {
        float pj = __shfl_sync(0xffffffffu, p, j, 8);
        if (pj > p1) { p2 = p1; p1 = pj; }
        else if (pj > p2) { p2 = pj; }
    }
    float calib = (c == 0) ? (1.0f - p1 + p2) : 0.f;
    __shared__ float red[256];
    __shared__ int lastFlag;
    red[threadIdx.x] = calib;
    __syncthreads();
    for (int d = 128; d > 0; d >>= 1) {
        if (threadIdx.x < d) red[threadIdx.x] += red[threadIdx.x + d];
        __syncthreads();
    }
    if (threadIdx.x == 0) {
        g_calib[blockIdx.x] = red[0];
        __threadfence();
        int t = atomicAdd(&g_done, 1);
        lastFlag = (t == NB8 - 1);
    }
    __syncthreads();
    if (lastFlag) {
        float sum2 = 0.f;
        for (int i2 = threadIdx.x; i2 < NB8; i2 += 256) sum2 += __ldcg(&g_calib[i2]);
        red[threadIdx.x] = sum2;
        __syncthreads();
        for (int d = 128; d > 0; d >>= 1) {
            if (threadIdx.x < d) red[threadIdx.x] += red[threadIdx.x + d];
            __syncthreads();
        }
        if (threadIdx.x == 0) out[700000] = red[0] / (float)GN;
    }
}

// ---------------- launch: gemm1 stays 4th submitted kernel (ncu window) ----------------
extern "C" void kernel_launch(void* const* d_in, const int* in_sizes, int n_in,
                              void* d_out, int out_size) {
    const float* x        = (const float*)d_in[0];
    const int*   ei       = (const int*)d_in[1];
    const float* mask     = (const float*)d_in[2];
    const float* W1       = (const float*)d_in[3];
    const float* att_s1   = (const float*)d_in[4];
    const float* att_d1   = (const float*)d_in[5];
    const float* b1       = (const float*)d_in[6];
    const float* W2       = (const float*)d_in[7];
    const float* att_s2   = (const float*)d_in[8];
    const float* att_d2   = (const float*)d_in[9];
    const float* b2       = (const float*)d_in[10];
    float* out = (float*)d_out;

    static cudaStream_t s2 = nullptr;
    static cudaEvent_t evFork = nullptr, evW = nullptr, evJoin = nullptr;
    if (s2 == nullptr) {
        cudaStreamCreateWithFlags(&s2, cudaStreamNonBlocking);
        cudaEventCreateWithFlags(&evFork, cudaEventDisableTiming);
        cudaEventCreateWithFlags(&evW, cudaEventDisableTiming);
        cudaEventCreateWithFlags(&evJoin, cudaEventDisableTiming);
        cudaFuncSetAttribute(k_gemm1_tc, cudaFuncAttributeMaxDynamicSharedMemorySize, SMEM_TOT);
    }

    const int TB = 256;
    int eg = (GE + TB - 1) / TB;

    cudaEventRecord(evFork, 0);
    cudaStreamWaitEvent(s2, evFork, 0);
    k_zero_wconv<<<NCHUNK, TB, 0, s2>>>(W1);      // #1
    cudaEventRecord(evW, s2);
    k_hist<<<eg, TB, 0, s2>>>(ei);                // #2
    k_scan<<<NCHUNK, TB, 0, s2>>>();              // #3
    cudaStreamWaitEvent(0, evW, 0);
    k_gemm1_tc<<<GM1_GRID, TB, SMEM_TOT>>>(x, att_s1, att_d1);   // #4 (main)
    k_scatter<<<eg, TB, 0, s2>>>(ei);             // #5 (side)
    cudaEventRecord(evJoin, s2);
    cudaStreamWaitEvent(0, evJoin, 0);

    k_agg1<<<NB8, TB>>>(b1, mask, W2, att_s2, att_d2);   // #6
    k_agg2<<<NB8, TB>>>(b2, out);                        // #7 (final fused)
}